// round 1
// baseline (speedup 1.0000x reference)
#include <cuda_runtime.h>
#include <math.h>

#define NB 128
#define HH 1024
#define DD 1024
#define TT 256
#define G4 4096

// Scratch (allocation-free rule: __device__ globals)
__device__ float g_WsumT[(size_t)HH * G4];   // (Wih+Whh)^T, k-major [k][gatecol]
__device__ float g_WihT [(size_t)HH * G4];   // Wih^T, k-major
__device__ float g_WfcT [(size_t)HH * DD];   // Wfc^T, k-major [k][d]
__device__ float g_bsum [G4];                // bih + bhh
__device__ float g_c    [NB * HH];           // cell state (in-place)
__device__ float g_hs   [(size_t)TT * NB * HH];  // all hidden states [t][n][h]

// ---------------------------------------------------------------------------
// Prep: W_sum, transposes, bias sum. Runs once per launch (deterministic).
// ---------------------------------------------------------------------------
__global__ void prep_kernel(const float* __restrict__ Wih,
                            const float* __restrict__ Whh,
                            const float* __restrict__ bih,
                            const float* __restrict__ bhh,
                            const float* __restrict__ Wfc)
{
    size_t idx = (size_t)blockIdx.x * blockDim.x + threadIdx.x;
    size_t stride = (size_t)gridDim.x * blockDim.x;

    // W^T layout: i = k*4096 + col  (writes coalesced)
    for (size_t i = idx; i < (size_t)HH * G4; i += stride) {
        int k   = (int)(i >> 12);
        int col = (int)(i & 4095);
        float a = Wih[(size_t)col * HH + k];
        float b = Whh[(size_t)col * HH + k];
        g_WihT[i]  = a;
        g_WsumT[i] = a + b;
    }
    for (size_t i = idx; i < (size_t)HH * DD; i += stride) {
        int k   = (int)(i >> 10);
        int col = (int)(i & 1023);
        g_WfcT[i] = Wfc[(size_t)col * HH + k];
    }
    for (size_t i = idx; i < (size_t)G4; i += stride)
        g_bsum[i] = bih[i] + bhh[i];
}

// ---------------------------------------------------------------------------
// Packed f32x2 helpers (FFMA2: 2x fp32 FMA throughput vs FFMA-3reg rt=2)
// ---------------------------------------------------------------------------
__device__ __forceinline__ unsigned long long pack2(float x, float y) {
    unsigned long long r;
    asm("mov.b64 %0, {%1, %2};" : "=l"(r) : "f"(x), "f"(y));
    return r;
}
__device__ __forceinline__ void unpack2(unsigned long long v, float& x, float& y) {
    asm("mov.b64 {%0, %1}, %2;" : "=f"(x), "=f"(y) : "l"(v));
}
__device__ __forceinline__ void ffma2(unsigned long long& acc,
                                      unsigned long long a, unsigned long long b) {
    asm("fma.rn.f32x2 %0, %1, %2, %0;" : "+l"(acc) : "l"(a), "l"(b));
}

#define BK 64
#define AS_STRIDE 34     // [k][m] transposed stage, padded (8B-aligned pairs)
#define GS_STRIDE 132    // gates tile [m][128 gatecols], padded

// ---------------------------------------------------------------------------
// One LSTM step, fused GEMM + pointwise.
// CTA tile: 32 rows x 128 gatecols (= 32 hidden cols x 4 gates).
// grid = (H/32, N/32) = (32, 4) = 128 CTAs, 256 threads.
// Thread: one gatecol, 16 rows (as 8 f32x2 accumulators).
// A (x rows) staged k-major in SMEM -> LDS.64 gives packed row-pairs free.
// W streamed from L2 (k-major, coalesced).
// ---------------------------------------------------------------------------
__global__ void __launch_bounds__(256) lstm_step(const float* __restrict__ hT, int t)
{
    __shared__ float As[BK * AS_STRIDE];
    __shared__ float Gs[32 * GS_STRIDE];

    const float* x  = (t == 0) ? hT : (g_hs + (size_t)(t - 1) * (NB * HH));
    const float* WT = (t == 0) ? g_WihT : g_WsumT;

    int tid  = threadIdx.x;
    int gc   = tid & 127;        // local gate col 0..127
    int half = tid >> 7;         // row half 0/1
    int g    = gc >> 5;          // gate 0..3 (i,f,g,o)
    int jj   = gc & 31;          // hidden col within block
    int j0   = blockIdx.x * 32;
    int m0   = blockIdx.y * 32;
    int gcol = g * HH + j0 + jj; // global gate row / WT column

    const float* Wcol = WT + gcol;
    int mbase = half * 16;

    unsigned long long acc[8];
#pragma unroll
    for (int i = 0; i < 8; i++) acc[i] = 0ULL;

    for (int k0 = 0; k0 < HH; k0 += BK) {
        // Stage x[m0..m0+31][k0..k0+63] transposed: As[k][m]
#pragma unroll
        for (int j = 0; j < 2; j++) {
            int idx = tid + j * 256;          // 512 float4 total
            int m   = idx >> 4;               // 0..31
            int kq  = idx & 15;               // float4 index along k
            float4 v = *reinterpret_cast<const float4*>(
                x + (size_t)(m0 + m) * HH + k0 + kq * 4);
            As[(kq * 4 + 0) * AS_STRIDE + m] = v.x;
            As[(kq * 4 + 1) * AS_STRIDE + m] = v.y;
            As[(kq * 4 + 2) * AS_STRIDE + m] = v.z;
            As[(kq * 4 + 3) * AS_STRIDE + m] = v.w;
        }
        __syncthreads();

#pragma unroll 8
        for (int k = 0; k < BK; k++) {
            float wv = Wcol[(k0 + k) * G4];                 // L2-resident, coalesced
            unsigned long long wp = pack2(wv, wv);
            const float* arow = &As[k * AS_STRIDE + mbase];
#pragma unroll
            for (int mp = 0; mp < 8; mp++) {
                unsigned long long a2 =
                    *reinterpret_cast<const unsigned long long*>(arow + 2 * mp);
                ffma2(acc[mp], a2, wp);
            }
        }
        __syncthreads();
    }

    // Gates -> SMEM (with bias)
    float bias = g_bsum[gcol];
#pragma unroll
    for (int mp = 0; mp < 8; mp++) {
        float v0, v1;
        unpack2(acc[mp], v0, v1);
        Gs[(mbase + 2 * mp + 0) * GS_STRIDE + gc] = v0 + bias;
        Gs[(mbase + 2 * mp + 1) * GS_STRIDE + gc] = v1 + bias;
    }
    __syncthreads();

    // Pointwise LSTM update: 1024 cells / 256 threads
#pragma unroll
    for (int it = 0; it < 4; it++) {
        int cell = tid + it * 256;   // 0..1023
        int m    = cell >> 5;        // 0..31
        int jc   = cell & 31;
        float iv = Gs[m * GS_STRIDE +  0 + jc];
        float fv = Gs[m * GS_STRIDE + 32 + jc];
        float gv = Gs[m * GS_STRIDE + 64 + jc];
        float ov = Gs[m * GS_STRIDE + 96 + jc];
        iv = 1.0f / (1.0f + expf(-iv));
        fv = 1.0f / (1.0f + expf(-fv));
        gv = tanhf(gv);
        ov = 1.0f / (1.0f + expf(-ov));
        size_t gi = (size_t)(m0 + m) * HH + j0 + jc;
        float cp = (t == 0) ? 0.0f : g_c[gi];
        float cn = fv * cp + iv * gv;
        g_c[gi] = cn;
        g_hs[(size_t)t * (NB * HH) + gi] = ov * tanhf(cn);
    }
}

// ---------------------------------------------------------------------------
// Final FC: out[n][t][d] = hs[t][n][:] @ Wfc^T + b_fc
// hs flat rows r = t*128 + n. CTA: 32 rows x 128 d-cols.
// grid = (D/128, (T*N)/32) = (8, 1024)
// ---------------------------------------------------------------------------
__global__ void __launch_bounds__(256) fc_kernel(const float* __restrict__ bfc,
                                                 float* __restrict__ out)
{
    __shared__ float As[BK * AS_STRIDE];

    int tid  = threadIdx.x;
    int dc   = tid & 127;
    int half = tid >> 7;
    int d    = blockIdx.x * 128 + dc;
    int r0   = blockIdx.y * 32;
    int mbase = half * 16;

    const float* Wcol = g_WfcT + d;
    const float* x = g_hs + (size_t)r0 * HH;

    unsigned long long acc[8];
#pragma unroll
    for (int i = 0; i < 8; i++) acc[i] = 0ULL;

    for (int k0 = 0; k0 < HH; k0 += BK) {
#pragma unroll
        for (int j = 0; j < 2; j++) {
            int idx = tid + j * 256;
            int m   = idx >> 4;
            int kq  = idx & 15;
            float4 v = *reinterpret_cast<const float4*>(
                x + (size_t)m * HH + k0 + kq * 4);
            As[(kq * 4 + 0) * AS_STRIDE + m] = v.x;
            As[(kq * 4 + 1) * AS_STRIDE + m] = v.y;
            As[(kq * 4 + 2) * AS_STRIDE + m] = v.z;
            As[(kq * 4 + 3) * AS_STRIDE + m] = v.w;
        }
        __syncthreads();

#pragma unroll 8
        for (int k = 0; k < BK; k++) {
            float wv = Wcol[(k0 + k) * DD];
            unsigned long long wp = pack2(wv, wv);
            const float* arow = &As[k * AS_STRIDE + mbase];
#pragma unroll
            for (int mp = 0; mp < 8; mp++) {
                unsigned long long a2 =
                    *reinterpret_cast<const unsigned long long*>(arow + 2 * mp);
                ffma2(acc[mp], a2, wp);
            }
        }
        __syncthreads();
    }

    float bias = bfc[d];
#pragma unroll
    for (int mp = 0; mp < 8; mp++) {
        float v0, v1;
        unpack2(acc[mp], v0, v1);
        int r = r0 + mbase + 2 * mp;
        // r = tstep*128 + n  ->  out[((n*TT) + tstep)*DD + d]
        out[((size_t)(r & 127) * TT + (r >> 7)) * DD + d] = v0 + bias;
        r += 1;
        out[((size_t)(r & 127) * TT + (r >> 7)) * DD + d] = v1 + bias;
    }
}

// ---------------------------------------------------------------------------
extern "C" void kernel_launch(void* const* d_in, const int* in_sizes, int n_in,
                              void* d_out, int out_size)
{
    const float* hT  = (const float*)d_in[0];
    const float* Wih = (const float*)d_in[1];
    const float* Whh = (const float*)d_in[2];
    const float* bih = (const float*)d_in[3];
    const float* bhh = (const float*)d_in[4];
    const float* Wfc = (const float*)d_in[5];
    const float* bfc = (const float*)d_in[6];
    float* out = (float*)d_out;

    prep_kernel<<<2048, 256>>>(Wih, Whh, bih, bhh, Wfc);

    dim3 sgrid(HH / 32, NB / 32);           // (32, 4) = 128 CTAs
    for (int t = 0; t < TT; t++)
        lstm_step<<<sgrid, 256>>>(hT, t);

    dim3 fgrid(DD / 128, (TT * NB) / 32);   // (8, 1024)
    fc_kernel<<<fgrid, 256>>>(bfc, out);
}

// round 2
// speedup vs baseline: 1.8765x; 1.8765x over previous
#include <cuda_runtime.h>
#include <math.h>

#define NB 128
#define HH 1024
#define DD 1024
#define TT 256
#define G4 4096
#define KS 4          // K slices per step GEMM
#define KSL 256       // K per slice

// Scratch (__device__ globals: allocation-free rule)
__device__ float g_WsumT[(size_t)HH * G4];   // (Wih+Whh)^T, k-major [k][gatecol]
__device__ float g_WihT [(size_t)HH * G4];   // Wih^T, k-major
__device__ float g_WfcT [(size_t)HH * DD];   // Wfc^T, k-major [k][d]
__device__ float g_bsum [G4];                // bih + bhh
__device__ float g_c    [NB * HH];           // cell state
__device__ float g_part [(size_t)KS * NB * G4];      // K-slice partial gates
__device__ float g_hs   [(size_t)TT * NB * HH];      // hidden states [t][n][h]

// ---------------------------------------------------------------------------
__global__ void prep_kernel(const float* __restrict__ Wih,
                            const float* __restrict__ Whh,
                            const float* __restrict__ bih,
                            const float* __restrict__ bhh,
                            const float* __restrict__ Wfc)
{
    size_t idx = (size_t)blockIdx.x * blockDim.x + threadIdx.x;
    size_t stride = (size_t)gridDim.x * blockDim.x;

    for (size_t i = idx; i < (size_t)HH * G4; i += stride) {
        int k   = (int)(i >> 12);
        int col = (int)(i & 4095);
        float a = Wih[(size_t)col * HH + k];
        float b = Whh[(size_t)col * HH + k];
        g_WihT[i]  = a;
        g_WsumT[i] = a + b;
    }
    for (size_t i = idx; i < (size_t)HH * DD; i += stride) {
        int k   = (int)(i >> 10);
        int col = (int)(i & 1023);
        g_WfcT[i] = Wfc[(size_t)col * HH + k];
    }
    for (size_t i = idx; i < (size_t)G4; i += stride)
        g_bsum[i] = bih[i] + bhh[i];
}

// ---------------------------------------------------------------------------
// Packed f32x2 helpers
// ---------------------------------------------------------------------------
__device__ __forceinline__ unsigned long long pack2(float x, float y) {
    unsigned long long r;
    asm("mov.b64 %0, {%1, %2};" : "=l"(r) : "f"(x), "f"(y));
    return r;
}
__device__ __forceinline__ void unpack2(unsigned long long v, float& x, float& y) {
    asm("mov.b64 {%0, %1}, %2;" : "=f"(x), "=f"(y) : "l"(v));
}
__device__ __forceinline__ void ffma2(unsigned long long& acc,
                                      unsigned long long a, unsigned long long b) {
    asm("fma.rn.f32x2 %0, %1, %2, %0;" : "+l"(acc) : "l"(a), "l"(b));
}

#define BK 64
#define AS_STRIDE 34

// ---------------------------------------------------------------------------
// GEMM micro-kernel body shared by lstm_gemm and fc.
// CTA: 256 threads, tile 32 rows x 128 cols, micro-tile 8m x 2col.
//   gcp = tid&63 (col pair), mg = tid>>6 (8-row group)
// A staged k-major in SMEM (broadcast LDS.64); W streamed as LDG.64 (L2-hit).
// ---------------------------------------------------------------------------
struct Acc16 { unsigned long long a0[4]; unsigned long long a1[4]; };

__device__ __forceinline__ void gemm_tile(const float* __restrict__ x,  // [rows][K] at row m0
                                          const float* __restrict__ WT, // [K][ldw] col base included
                                          int ldw, int kcount,
                                          float* As, int tid, int gcp, int mg,
                                          Acc16& acc)
{
#pragma unroll
    for (int i = 0; i < 4; i++) { acc.a0[i] = 0ULL; acc.a1[i] = 0ULL; }

    for (int kb = 0; kb < kcount; kb += BK) {
#pragma unroll
        for (int j = 0; j < 2; j++) {
            int idx = tid + j * 256;          // 512 float4
            int m   = idx >> 4;               // 0..31
            int kq  = idx & 15;
            float4 v = *reinterpret_cast<const float4*>(x + (size_t)m * HH + kb + kq * 4);
            As[(kq * 4 + 0) * AS_STRIDE + m] = v.x;
            As[(kq * 4 + 1) * AS_STRIDE + m] = v.y;
            As[(kq * 4 + 2) * AS_STRIDE + m] = v.z;
            As[(kq * 4 + 3) * AS_STRIDE + m] = v.w;
        }
        __syncthreads();

        const float* Wp = WT + (size_t)kb * ldw + 2 * gcp;
#pragma unroll 8
        for (int k = 0; k < BK; k++) {
            float2 w = *reinterpret_cast<const float2*>(Wp + (size_t)k * ldw);
            unsigned long long wp0 = pack2(w.x, w.x);
            unsigned long long wp1 = pack2(w.y, w.y);
            const float* arow = &As[k * AS_STRIDE + mg * 8];
#pragma unroll
            for (int mp = 0; mp < 4; mp++) {
                unsigned long long a2 =
                    *reinterpret_cast<const unsigned long long*>(arow + 2 * mp);
                ffma2(acc.a0[mp], a2, wp0);
                ffma2(acc.a1[mp], a2, wp1);
            }
        }
        __syncthreads();
    }
}

// ---------------------------------------------------------------------------
// Per-step gate GEMM, K-split. grid (32 gc-tiles, 4 m-tiles, 4 k-slices).
// Writes partial gates to g_part[ks].
// ---------------------------------------------------------------------------
__global__ void __launch_bounds__(256) lstm_gemm(const float* __restrict__ hT, int t)
{
    __shared__ float As[BK * AS_STRIDE];

    int tid = threadIdx.x;
    int gcp = tid & 63;
    int mg  = tid >> 6;
    int gcbase = blockIdx.x * 128;
    int m0     = blockIdx.y * 32;
    int ks     = blockIdx.z;

    const float* x  = ((t == 0) ? hT : (g_hs + (size_t)(t - 1) * (NB * HH)))
                      + (size_t)m0 * HH + ks * KSL;
    const float* WT = ((t == 0) ? g_WihT : g_WsumT)
                      + (size_t)ks * KSL * G4 + gcbase;

    Acc16 acc;
    gemm_tile(x, WT, G4, KSL, As, tid, gcp, mg, acc);

    // store partials: rows m0+mg*8+2mp(+1), cols gcbase+2gcp(+1) as float2
    float* out = g_part + ((size_t)ks * NB + m0 + mg * 8) * G4 + gcbase + 2 * gcp;
#pragma unroll
    for (int mp = 0; mp < 4; mp++) {
        float x0, x1, y0, y1;
        unpack2(acc.a0[mp], x0, x1);
        unpack2(acc.a1[mp], y0, y1);
        *reinterpret_cast<float2*>(out + (size_t)(2 * mp)     * G4) = make_float2(x0, y0);
        *reinterpret_cast<float2*>(out + (size_t)(2 * mp + 1) * G4) = make_float2(x1, y1);
    }
}

// ---------------------------------------------------------------------------
// Pointwise: sum K-slice partials + bias, activations, c/h update.
// 32768 float4 cells. grid 128 x 256 threads.
// ---------------------------------------------------------------------------
__device__ __forceinline__ float4 sig4(float4 v) {
    v.x = 1.0f / (1.0f + expf(-v.x));
    v.y = 1.0f / (1.0f + expf(-v.y));
    v.z = 1.0f / (1.0f + expf(-v.z));
    v.w = 1.0f / (1.0f + expf(-v.w));
    return v;
}
__device__ __forceinline__ float4 tanh4(float4 v) {
    v.x = tanhf(v.x); v.y = tanhf(v.y); v.z = tanhf(v.z); v.w = tanhf(v.w);
    return v;
}
__device__ __forceinline__ float4 add4(float4 a, float4 b) {
    return make_float4(a.x + b.x, a.y + b.y, a.z + b.z, a.w + b.w);
}

__global__ void __launch_bounds__(256) lstm_pointwise(int t)
{
    int idx = blockIdx.x * 256 + threadIdx.x;   // 0..32767
    int m = idx >> 8;
    int j = (idx & 255) * 4;

    float4 gate[4];
#pragma unroll
    for (int g = 0; g < 4; g++) {
        size_t off = (size_t)m * G4 + g * HH + j;
        float4 s = *reinterpret_cast<const float4*>(g_part + off);
#pragma unroll
        for (int ks = 1; ks < KS; ks++)
            s = add4(s, *reinterpret_cast<const float4*>(g_part + (size_t)ks * NB * G4 + off));
        gate[g] = add4(s, *reinterpret_cast<const float4*>(g_bsum + g * HH + j));
    }

    float4 iv = sig4(gate[0]);
    float4 fv = sig4(gate[1]);
    float4 gv = tanh4(gate[2]);
    float4 ov = sig4(gate[3]);

    size_t ci = (size_t)m * HH + j;
    float4 cp = (t == 0) ? make_float4(0.f, 0.f, 0.f, 0.f)
                         : *reinterpret_cast<const float4*>(g_c + ci);
    float4 cn = make_float4(fv.x * cp.x + iv.x * gv.x,
                            fv.y * cp.y + iv.y * gv.y,
                            fv.z * cp.z + iv.z * gv.z,
                            fv.w * cp.w + iv.w * gv.w);
    *reinterpret_cast<float4*>(g_c + ci) = cn;

    float4 tc = tanh4(cn);
    float4 hn = make_float4(ov.x * tc.x, ov.y * tc.y, ov.z * tc.z, ov.w * tc.w);
    *reinterpret_cast<float4*>(g_hs + (size_t)t * (NB * HH) + ci) = hn;
}

// ---------------------------------------------------------------------------
// Final FC: out[n][t][d] = hs[t][n][:] @ WfcT + b_fc.
// Rows r = t*128 + n (32768). grid (8 d-tiles, 1024 r-tiles).
// ---------------------------------------------------------------------------
__global__ void __launch_bounds__(256) fc_kernel(const float* __restrict__ bfc,
                                                 float* __restrict__ out)
{
    __shared__ float As[BK * AS_STRIDE];

    int tid = threadIdx.x;
    int gcp = tid & 63;
    int mg  = tid >> 6;
    int dbase = blockIdx.x * 128;
    int r0    = blockIdx.y * 32;

    const float* x  = g_hs + (size_t)r0 * HH;
    const float* WT = g_WfcT + dbase;

    Acc16 acc;
    gemm_tile(x, WT, DD, HH, As, tid, gcp, mg, acc);

    int d = dbase + 2 * gcp;
    float b0 = bfc[d], b1 = bfc[d + 1];
#pragma unroll
    for (int mp = 0; mp < 4; mp++) {
        float x0, x1, y0, y1;
        unpack2(acc.a0[mp], x0, x1);
        unpack2(acc.a1[mp], y0, y1);
        int r = r0 + mg * 8 + 2 * mp;
        *reinterpret_cast<float2*>(out + ((size_t)(r & 127) * TT + (r >> 7)) * DD + d)
            = make_float2(x0 + b0, y0 + b1);
        r += 1;
        *reinterpret_cast<float2*>(out + ((size_t)(r & 127) * TT + (r >> 7)) * DD + d)
            = make_float2(x1 + b0, y1 + b1);
    }
}

// ---------------------------------------------------------------------------
extern "C" void kernel_launch(void* const* d_in, const int* in_sizes, int n_in,
                              void* d_out, int out_size)
{
    const float* hT  = (const float*)d_in[0];
    const float* Wih = (const float*)d_in[1];
    const float* Whh = (const float*)d_in[2];
    const float* bih = (const float*)d_in[3];
    const float* bhh = (const float*)d_in[4];
    const float* Wfc = (const float*)d_in[5];
    const float* bfc = (const float*)d_in[6];
    float* out = (float*)d_out;

    prep_kernel<<<2048, 256>>>(Wih, Whh, bih, bhh, Wfc);

    dim3 ggrid(G4 / 128, NB / 32, KS);      // (32, 4, 4) = 512 CTAs
    for (int t = 0; t < TT; t++) {
        lstm_gemm<<<ggrid, 256>>>(hT, t);
        lstm_pointwise<<<128, 256>>>(t);
    }

    dim3 fgrid(DD / 128, (TT * NB) / 32);   // (8, 1024)
    fc_kernel<<<fgrid, 256>>>(bfc, out);
}